// round 2
// baseline (speedup 1.0000x reference)
#include <cuda_runtime.h>

#define Bb 16
#define Hh 256
#define Ww 256
#define Cc 64
#define M1m 20
#define M2m 20

// Scratch (device globals; no allocation allowed)
__device__ float2 g_A [Bb*Hh*M2m*Cc];   // forward w-transform   [b][h][ky][c]
__device__ float2 g_M [Bb*M2m*M1m*Cc];  // forward modes         [b][ky][kx][c]
__device__ float2 g_Mo[Bb*M2m*M1m*Cc];  // mixed modes (scaled)  [b][ky][kx][c]
__device__ float2 g_T [Bb*Hh*M2m*Cc];   // inverse h-expand      [b][h][ky][c]

#define TWO_PI_OVER_256 0.0245436926061702596f

// ---- f32x2 helpers (packed fp32 pair in one 64-bit register) --------------
__device__ __forceinline__ double ffma2(double a, double b, double c) {
    double d;
    asm("fma.rn.f32x2 %0, %1, %2, %3;" : "=d"(d) : "d"(a), "d"(b), "d"(c));
    return d;
}
__device__ __forceinline__ double dup2(float x) {
    double d; asm("mov.b64 %0, {%1, %1};" : "=d"(d) : "f"(x)); return d;
}
__device__ __forceinline__ float2 up2(double d) {
    float2 f; asm("mov.b64 {%0, %1}, %2;" : "=f"(f.x), "=f"(f.y) : "d"(d));
    return f;
}

// ---------------------------------------------------------------------------
// K1: A[b,h,ky,c] = sum_w P[b,h,w,c] * e^{-2*pi*i*ky*w/W}
// block = (h, b); 160 threads = 20 ky * 8 c-groups of 8
// ---------------------------------------------------------------------------
__global__ void __launch_bounds__(160) k_fwd_w(const float* __restrict__ pts) {
    extern __shared__ float sm[];
    float* sP = sm;                          // 16384 floats  [w][c]
    float2* tcs = (float2*)(sm + Ww*Cc);     // 256 x (cos, -sin)
    const int h = blockIdx.x, b = blockIdx.y;
    const int tid = threadIdx.x;
    const float* prow = pts + ((size_t)(b*Hh + h))*(Ww*Cc);
    for (int i = tid; i < (Ww*Cc)/4; i += 160)
        ((float4*)sP)[i] = ((const float4*)prow)[i];
    for (int i = tid; i < 256; i += 160) {
        float s, c; sincosf((float)i * TWO_PI_OVER_256, &s, &c);
        tcs[i] = make_float2(c, -s);
    }
    __syncthreads();

    const int cg = tid & 7, ky = tid >> 3;
    const int c0 = cg * 8;

    double accre[4] = {0,0,0,0}, accim[4] = {0,0,0,0};
    int t = 0;
    #pragma unroll 4
    for (int w = 0; w < Ww; ++w) {
        double2 pA = *(const double2*)(sP + w*Cc + c0);
        double2 pB = *(const double2*)(sP + w*Cc + c0 + 4);
        float2 cs = tcs[t];
        double dc = dup2(cs.x), dn = dup2(cs.y);
        accre[0] = ffma2(dc, pA.x, accre[0]);
        accre[1] = ffma2(dc, pA.y, accre[1]);
        accre[2] = ffma2(dc, pB.x, accre[2]);
        accre[3] = ffma2(dc, pB.y, accre[3]);
        accim[0] = ffma2(dn, pA.x, accim[0]);
        accim[1] = ffma2(dn, pA.y, accim[1]);
        accim[2] = ffma2(dn, pB.x, accim[2]);
        accim[3] = ffma2(dn, pB.y, accim[3]);
        t = (t + ky) & 255;
    }
    float2* dst = g_A + (((size_t)(b*Hh + h))*M2m + ky)*Cc + c0;
    #pragma unroll
    for (int cp = 0; cp < 4; ++cp) {
        float2 r = up2(accre[cp]), im = up2(accim[cp]);
        *(float4*)(dst + 2*cp) = make_float4(r.x, im.x, r.y, im.y);
    }
}

// ---------------------------------------------------------------------------
// K2: M[b,ky,kx,c] = sum_h A[b,h,ky,c] * e^{-2*pi*i*(kx-10)*h/H}
// block = (ky, b); 128 threads = 2 kx-groups(10 each, as 5 pairs) * 64 c
// twiddles precomputed per h-chunk so kx-pairs load as LDS.64
// ---------------------------------------------------------------------------
#define HT2 32
__global__ void __launch_bounds__(128) k_fwd_h() {
    __shared__ float2 sA[HT2*Cc];           // 16 KB
    __shared__ float sCv[HT2*M1m];          // cos per (hh,kx)
    __shared__ float sSv[HT2*M1m];          // sin per (hh,kx)
    __shared__ float2 tbl[256];
    const int ky = blockIdx.x, b = blockIdx.y;
    const int tid = threadIdx.x;
    for (int i = tid; i < 256; i += 128) {
        float s, c; sincosf((float)i * TWO_PI_OVER_256, &s, &c);
        tbl[i] = make_float2(c, s);
    }
    const int cc = tid & 63, kg = tid >> 6;
    double aar[5] = {0,0,0,0,0}, aai[5] = {0,0,0,0,0};
    __syncthreads();

    for (int h0 = 0; h0 < Hh; h0 += HT2) {
        __syncthreads();
        for (int i = tid; i < HT2*Cc; i += 128)
            sA[i] = g_A[(((size_t)(b*Hh + h0 + (i >> 6)))*M2m + ky)*Cc + (i & 63)];
        for (int i = tid; i < HT2*M1m; i += 128) {
            int hh = i / M1m, kx = i - hh*M1m;
            float2 cs = tbl[((kx + 246) * (h0 + hh)) & 255];
            sCv[i] = cs.x; sSv[i] = cs.y;
        }
        __syncthreads();
        #pragma unroll 2
        for (int hh = 0; hh < HT2; ++hh) {
            float2 a = sA[hh*Cc + cc];
            double dax = dup2(a.x), day = dup2(a.y), dnx = dup2(-a.x);
            const float* cvp = sCv + hh*M1m + kg*10;
            const float* svp = sSv + hh*M1m + kg*10;
            #pragma unroll
            for (int p = 0; p < 5; ++p) {
                double cp = *(const double*)(cvp + 2*p);
                double sp = *(const double*)(svp + 2*p);
                aar[p] = ffma2(dax, cp, aar[p]);
                aar[p] = ffma2(day, sp, aar[p]);
                aai[p] = ffma2(day, cp, aai[p]);
                aai[p] = ffma2(dnx, sp, aai[p]);
            }
        }
    }
    #pragma unroll
    for (int p = 0; p < 5; ++p) {
        int kx = kg*10 + 2*p;
        float2 r = up2(aar[p]), im = up2(aai[p]);
        size_t base = (((size_t)(b*M2m + ky))*M1m + kx)*Cc + cc;
        g_M[base]      = make_float2(r.x, im.x);
        g_M[base + Cc] = make_float2(r.y, im.y);
    }
}

// ---------------------------------------------------------------------------
// K3: channel mix (complex 64x64 per mode) + fold alpha_ky/(H*W)
// block = kx*20+ky (400 blocks); 256 threads
// ---------------------------------------------------------------------------
__global__ void __launch_bounds__(256) k_mix(const float* __restrict__ kr,
                                             const float* __restrict__ ki) {
    __shared__ float sKr[64*65];
    __shared__ float sKi[64*65];
    __shared__ float2 sMin[16*64];
    const int kx = blockIdx.x / M2m, ky = blockIdx.x % M2m;
    const int tid = threadIdx.x;
    const size_t kbase = ((size_t)(kx*M2m + ky))*Cc*Cc;
    for (int idx = tid; idx < 64*64; idx += 256) {
        int i = idx >> 6, j = idx & 63;
        sKr[i*65 + j] = kr[kbase + idx];
        sKi[i*65 + j] = ki[kbase + idx];
    }
    for (int idx = tid; idx < 16*64; idx += 256) {
        int bb = idx >> 6, j = idx & 63;
        sMin[idx] = g_M[(((size_t)(bb*M2m + ky))*M1m + kx)*Cc + j];
    }
    __syncthreads();
    const float sc = (ky == 0 ? 1.0f : 2.0f) * (1.0f/65536.0f);
    const int i = tid & 63, bq = tid >> 6;
    float ar[4] = {0,0,0,0}, ai[4] = {0,0,0,0};
    for (int j = 0; j < 64; ++j) {
        float krv = sKr[i*65 + j], kiv = sKi[i*65 + j];
        #pragma unroll
        for (int r = 0; r < 4; ++r) {
            float2 m = sMin[(bq*4 + r)*64 + j];
            ar[r] += krv*m.x - kiv*m.y;
            ai[r] += krv*m.y + kiv*m.x;
        }
    }
    #pragma unroll
    for (int r = 0; r < 4; ++r) {
        int bb = bq*4 + r;
        g_Mo[(((size_t)(bb*M2m + ky))*M1m + kx)*Cc + i] =
            make_float2(ar[r]*sc, ai[r]*sc);
    }
}

// ---------------------------------------------------------------------------
// K4: T[b,h,ky,c] = sum_kx Mo[b,ky,kx,c] * e^{+2*pi*i*(kx-10)*h/H}
// block = (ky, b, hchunk of 64); 256 threads = 4 h-groups * 64 c
// (mr,mr)/(mi,mi) dups hoisted; acc = (ar,ai) packed; two packed tables
// ---------------------------------------------------------------------------
__global__ void __launch_bounds__(256) k_inv_h() {
    __shared__ float2 sMo[M1m*Cc];
    __shared__ float2 tA[256];   // (cos, sin)
    __shared__ float2 tB[256];   // (-sin, cos)
    const int ky = blockIdx.x, b = blockIdx.y, hc = blockIdx.z;
    const int tid = threadIdx.x;
    {
        float s, c; sincosf((float)tid * TWO_PI_OVER_256, &s, &c);
        tA[tid] = make_float2(c, s);
        tB[tid] = make_float2(-s, c);
    }
    for (int i = tid; i < M1m*Cc; i += 256)
        sMo[i] = g_Mo[((size_t)(b*M2m + ky))*M1m*Cc + i];
    __syncthreads();
    const int cc = tid & 63, hg = tid >> 6;
    double dmr[M1m], dmi[M1m];
    #pragma unroll
    for (int kx = 0; kx < M1m; ++kx) {
        float2 m = sMo[kx*Cc + cc];
        dmr[kx] = dup2(m.x); dmi[kx] = dup2(m.y);
    }
    #pragma unroll 2
    for (int it = 0; it < 16; ++it) {
        int h = hc*64 + hg + 4*it;
        double acc = 0.0;
        int t = (246*h) & 255;
        #pragma unroll
        for (int kx = 0; kx < M1m; ++kx) {
            acc = ffma2(dmr[kx], *(const double*)&tA[t], acc);
            acc = ffma2(dmi[kx], *(const double*)&tB[t], acc);
            t = (t + h) & 255;
        }
        *(double*)&g_T[(((size_t)(b*Hh + h))*M2m + ky)*Cc + cc] = acc;
    }
}

// ---------------------------------------------------------------------------
// K5: out[b,h,w,c] = sum_ky (Tr*cos - Ti*sin) + P @ (Wl^T + I)
// block = (h, b); 256 threads; each thread an 8w x 8c tile (one pass)
// ---------------------------------------------------------------------------
__global__ void __launch_bounds__(256) k_final(const float* __restrict__ pts,
                                               const float* __restrict__ wl,
                                               float* __restrict__ out) {
    extern __shared__ float sm[];
    float* sP  = sm;                  // 16384  [w][c]
    float* sW  = sP + Ww*Cc;          // 4096   [j][c]  (wl^T + I)
    float* sTr = sW + Cc*Cc;          // 1280   [ky][c]
    float* sTn = sTr + M2m*Cc;        // 1280   [ky][c]  (-Ti)
    float2* tcs = (float2*)(sTn + M2m*Cc);   // 256 x (cos, sin)
    const int h = blockIdx.x, b = blockIdx.y;
    const int tid = threadIdx.x;
    const size_t rowbase = ((size_t)(b*Hh + h))*(Ww*Cc);

    for (int i = tid; i < (Ww*Cc)/4; i += 256)
        ((float4*)sP)[i] = ((const float4*)(pts + rowbase))[i];
    for (int idx = tid; idx < Cc*Cc; idx += 256) {
        int c = idx >> 6, j = idx & 63;
        sW[j*64 + c] = wl[idx] + ((c == j) ? 1.0f : 0.0f);
    }
    {
        const float2* tsrc = g_T + ((size_t)(b*Hh + h))*M2m*Cc;
        for (int i = tid; i < M2m*Cc; i += 256) {
            float2 v = tsrc[i];
            sTr[i] = v.x; sTn[i] = -v.y;
        }
    }
    {
        float s, c; sincosf((float)tid * TWO_PI_OVER_256, &s, &c);
        tcs[tid] = make_float2(c, s);
    }
    __syncthreads();

    const int tc = tid & 7, tw = tid >> 3;
    const int c0 = tc * 8, w0 = tw * 8;

    double acc[8][4];
    #pragma unroll
    for (int w = 0; w < 8; ++w)
        #pragma unroll
        for (int cp = 0; cp < 4; ++cp) acc[w][cp] = 0.0;

    // linear GEMM: acc[w][cp] += P[w0+w][j] * (Wl^T+I)[j][c-pair]
    #pragma unroll 2
    for (int j = 0; j < Cc; j += 2) {
        double2 B0a = *(const double2*)(sW + j*Cc + c0);
        double2 B0b = *(const double2*)(sW + j*Cc + c0 + 4);
        double2 B1a = *(const double2*)(sW + (j+1)*Cc + c0);
        double2 B1b = *(const double2*)(sW + (j+1)*Cc + c0 + 4);
        #pragma unroll
        for (int w = 0; w < 8; ++w) {
            float2 p = *(const float2*)(sP + (w0+w)*Cc + j);
            double d0 = dup2(p.x), d1 = dup2(p.y);
            acc[w][0] = ffma2(d0, B0a.x, acc[w][0]);
            acc[w][1] = ffma2(d0, B0a.y, acc[w][1]);
            acc[w][2] = ffma2(d0, B0b.x, acc[w][2]);
            acc[w][3] = ffma2(d0, B0b.y, acc[w][3]);
            acc[w][0] = ffma2(d1, B1a.x, acc[w][0]);
            acc[w][1] = ffma2(d1, B1a.y, acc[w][1]);
            acc[w][2] = ffma2(d1, B1b.x, acc[w][2]);
            acc[w][3] = ffma2(d1, B1b.y, acc[w][3]);
        }
    }

    // spectral: acc[w][cp] += Tr*cos + (-Ti)*sin
    #pragma unroll 1
    for (int ky = 0; ky < M2m; ++ky) {
        double2 ta = *(const double2*)(sTr + ky*Cc + c0);
        double2 tb = *(const double2*)(sTr + ky*Cc + c0 + 4);
        double2 na = *(const double2*)(sTn + ky*Cc + c0);
        double2 nb = *(const double2*)(sTn + ky*Cc + c0 + 4);
        int t = (ky * w0) & 255;
        #pragma unroll
        for (int w = 0; w < 8; ++w) {
            float2 cs = tcs[t];
            double dc = dup2(cs.x), ds = dup2(cs.y);
            acc[w][0] = ffma2(dc, ta.x, acc[w][0]);
            acc[w][1] = ffma2(dc, ta.y, acc[w][1]);
            acc[w][2] = ffma2(dc, tb.x, acc[w][2]);
            acc[w][3] = ffma2(dc, tb.y, acc[w][3]);
            acc[w][0] = ffma2(ds, na.x, acc[w][0]);
            acc[w][1] = ffma2(ds, na.y, acc[w][1]);
            acc[w][2] = ffma2(ds, nb.x, acc[w][2]);
            acc[w][3] = ffma2(ds, nb.y, acc[w][3]);
            t = (t + ky) & 255;
        }
    }

    // store
    #pragma unroll
    for (int w = 0; w < 8; ++w) {
        float2 a0 = up2(acc[w][0]), a1 = up2(acc[w][1]);
        float2 a2 = up2(acc[w][2]), a3 = up2(acc[w][3]);
        float* op = out + rowbase + (size_t)(w0+w)*Cc + c0;
        *(float4*)(op)     = make_float4(a0.x, a0.y, a1.x, a1.y);
        *(float4*)(op + 4) = make_float4(a2.x, a2.y, a3.x, a3.y);
    }
}

// ---------------------------------------------------------------------------
extern "C" void kernel_launch(void* const* d_in, const int* in_sizes, int n_in,
                              void* d_out, int out_size) {
    (void)in_sizes; (void)n_in; (void)out_size;
    const float* pts = (const float*)d_in[0];
    const float* kr  = (const float*)d_in[1];
    const float* ki  = (const float*)d_in[2];
    const float* wl  = (const float*)d_in[3];
    float* out = (float*)d_out;

    const int sm1 = Ww*Cc*(int)sizeof(float) + 256*(int)sizeof(float2);   // ~66 KB
    const int sm5 = (Ww*Cc + Cc*Cc + 2*M2m*Cc)*(int)sizeof(float)
                  + 256*(int)sizeof(float2);                              // ~92 KB
    cudaFuncSetAttribute(k_fwd_w, cudaFuncAttributeMaxDynamicSharedMemorySize, sm1);
    cudaFuncSetAttribute(k_final, cudaFuncAttributeMaxDynamicSharedMemorySize, sm5);

    k_fwd_w<<<dim3(Hh, Bb), 160, sm1>>>(pts);
    k_fwd_h<<<dim3(M2m, Bb), 128>>>();
    k_mix  <<<M1m*M2m, 256>>>(kr, ki);
    k_inv_h<<<dim3(M2m, Bb, 4), 256>>>();
    k_final<<<dim3(Hh, Bb), 256, sm5>>>(pts, wl, out);
}

// round 3
// speedup vs baseline: 1.0435x; 1.0435x over previous
#include <cuda_runtime.h>

#define Bb 16
#define Hh 256
#define Ww 256
#define Cc 64
#define M1m 20
#define M2m 20

// Scratch (device globals; no allocation allowed)
__device__ float2 g_A [Bb*Hh*M2m*Cc];   // forward w-transform   [b][h][ky][c]
__device__ float2 g_M [Bb*M2m*M1m*Cc];  // forward modes         [b][ky][kx][c]
__device__ float2 g_Mo[Bb*M2m*M1m*Cc];  // mixed modes (scaled)  [b][ky][kx][c]
__device__ float2 g_T [Bb*Hh*M2m*Cc];   // inverse h-expand      [b][h][ky][c]

#define TWO_PI_OVER_256 0.0245436926061702596f

// ---- f32x2 helpers (used ONLY in K2/K4 where they measurably won) ---------
__device__ __forceinline__ double ffma2(double a, double b, double c) {
    double d;
    asm("fma.rn.f32x2 %0, %1, %2, %3;" : "=d"(d) : "d"(a), "d"(b), "d"(c));
    return d;
}
__device__ __forceinline__ double dup2(float x) {
    double d; asm("mov.b64 %0, {%1, %1};" : "=d"(d) : "f"(x)); return d;
}
__device__ __forceinline__ float2 up2(double d) {
    float2 f; asm("mov.b64 {%0, %1}, %2;" : "=f"(f.x), "=f"(f.y) : "d"(d));
    return f;
}

// ---------------------------------------------------------------------------
// K1: A[b,h,ky,c] = sum_w P[b,h,w,c] * e^{-2*pi*i*ky*w/W}
// block=(h,b); 160 threads = 20 ky * 4 c-groups(16ch) * 2 w-split
// fp32 FFMA; packed (cos,-sin) table; smem partial reduction across w-split
// ---------------------------------------------------------------------------
__global__ void __launch_bounds__(160) k_fwd_w(const float* __restrict__ pts) {
    extern __shared__ float sm[];
    float* sP = sm;                          // 16384 floats [w][c]
    float2* tcs = (float2*)(sm + Ww*Cc);     // 256 x (cos, -sin)
    const int h = blockIdx.x, b = blockIdx.y;
    const int tid = threadIdx.x;
    const float* prow = pts + ((size_t)(b*Hh + h))*(Ww*Cc);
    for (int i = tid; i < (Ww*Cc)/4; i += 160)
        ((float4*)sP)[i] = ((const float4*)prow)[i];
    for (int i = tid; i < 256; i += 160) {
        float s, c; sincosf((float)i * TWO_PI_OVER_256, &s, &c);
        tcs[i] = make_float2(c, -s);
    }
    __syncthreads();

    const int ky = tid >> 3;           // 0..19
    const int cg = (tid >> 1) & 3;     // 0..3
    const int ws = tid & 1;            // 0..1
    const int c0 = cg * 16;

    float r[16], q[16];
    #pragma unroll
    for (int k = 0; k < 16; ++k) { r[k] = 0.f; q[k] = 0.f; }

    int t = (ky * (ws * 128)) & 255;
    const int wbeg = ws * 128;
    #pragma unroll 2
    for (int w = wbeg; w < wbeg + 128; ++w) {
        const float* pr = sP + w*Cc + c0;
        float4 pA = *(const float4*)(pr);
        float4 pB = *(const float4*)(pr + 4);
        float4 pC = *(const float4*)(pr + 8);
        float4 pD = *(const float4*)(pr + 12);
        float2 cs = tcs[t];
        float cv = cs.x, ns = cs.y;
        r[0]  += pA.x*cv; q[0]  += pA.x*ns;
        r[1]  += pA.y*cv; q[1]  += pA.y*ns;
        r[2]  += pA.z*cv; q[2]  += pA.z*ns;
        r[3]  += pA.w*cv; q[3]  += pA.w*ns;
        r[4]  += pB.x*cv; q[4]  += pB.x*ns;
        r[5]  += pB.y*cv; q[5]  += pB.y*ns;
        r[6]  += pB.z*cv; q[6]  += pB.z*ns;
        r[7]  += pB.w*cv; q[7]  += pB.w*ns;
        r[8]  += pC.x*cv; q[8]  += pC.x*ns;
        r[9]  += pC.y*cv; q[9]  += pC.y*ns;
        r[10] += pC.z*cv; q[10] += pC.z*ns;
        r[11] += pC.w*cv; q[11] += pC.w*ns;
        r[12] += pD.x*cv; q[12] += pD.x*ns;
        r[13] += pD.y*cv; q[13] += pD.y*ns;
        r[14] += pD.z*cv; q[14] += pD.z*ns;
        r[15] += pD.w*cv; q[15] += pD.w*ns;
        t = (t + ky) & 255;
    }

    // reduce the two w-split halves via smem (reuse sP)
    __syncthreads();
    if (ws == 1) {
        float* buf = sP + (ky*4 + cg)*32;
        #pragma unroll
        for (int k = 0; k < 16; ++k) { buf[k] = r[k]; buf[16+k] = q[k]; }
    }
    __syncthreads();
    if (ws == 0) {
        const float* buf = sP + (ky*4 + cg)*32;
        #pragma unroll
        for (int k = 0; k < 16; ++k) { r[k] += buf[k]; q[k] += buf[16+k]; }
        float2* dst = g_A + (((size_t)(b*Hh + h))*M2m + ky)*Cc + c0;
        #pragma unroll
        for (int k = 0; k < 8; ++k)
            *(float4*)(dst + 2*k) = make_float4(r[2*k], q[2*k], r[2*k+1], q[2*k+1]);
    }
}

// ---------------------------------------------------------------------------
// K2: M[b,ky,kx,c] = sum_h A[b,h,ky,c] * e^{-2*pi*i*(kx-10)*h/H}
// (kept from round 2 — f32x2 version)
// ---------------------------------------------------------------------------
#define HT2 32
__global__ void __launch_bounds__(128) k_fwd_h() {
    __shared__ float2 sA[HT2*Cc];
    __shared__ float sCv[HT2*M1m];
    __shared__ float sSv[HT2*M1m];
    __shared__ float2 tbl[256];
    const int ky = blockIdx.x, b = blockIdx.y;
    const int tid = threadIdx.x;
    for (int i = tid; i < 256; i += 128) {
        float s, c; sincosf((float)i * TWO_PI_OVER_256, &s, &c);
        tbl[i] = make_float2(c, s);
    }
    const int cc = tid & 63, kg = tid >> 6;
    double aar[5] = {0,0,0,0,0}, aai[5] = {0,0,0,0,0};
    __syncthreads();

    for (int h0 = 0; h0 < Hh; h0 += HT2) {
        __syncthreads();
        for (int i = tid; i < HT2*Cc; i += 128)
            sA[i] = g_A[(((size_t)(b*Hh + h0 + (i >> 6)))*M2m + ky)*Cc + (i & 63)];
        for (int i = tid; i < HT2*M1m; i += 128) {
            int hh = i / M1m, kx = i - hh*M1m;
            float2 cs = tbl[((kx + 246) * (h0 + hh)) & 255];
            sCv[i] = cs.x; sSv[i] = cs.y;
        }
        __syncthreads();
        #pragma unroll 2
        for (int hh = 0; hh < HT2; ++hh) {
            float2 a = sA[hh*Cc + cc];
            double dax = dup2(a.x), day = dup2(a.y), dnx = dup2(-a.x);
            const float* cvp = sCv + hh*M1m + kg*10;
            const float* svp = sSv + hh*M1m + kg*10;
            #pragma unroll
            for (int p = 0; p < 5; ++p) {
                double cp = *(const double*)(cvp + 2*p);
                double sp = *(const double*)(svp + 2*p);
                aar[p] = ffma2(dax, cp, aar[p]);
                aar[p] = ffma2(day, sp, aar[p]);
                aai[p] = ffma2(day, cp, aai[p]);
                aai[p] = ffma2(dnx, sp, aai[p]);
            }
        }
    }
    #pragma unroll
    for (int p = 0; p < 5; ++p) {
        int kx = kg*10 + 2*p;
        float2 r = up2(aar[p]), im = up2(aai[p]);
        size_t base = (((size_t)(b*M2m + ky))*M1m + kx)*Cc + cc;
        g_M[base]      = make_float2(r.x, im.x);
        g_M[base + Cc] = make_float2(r.y, im.y);
    }
}

// ---------------------------------------------------------------------------
// K3: channel mix (complex 64x64 per mode) + fold alpha_ky/(H*W)
// ---------------------------------------------------------------------------
__global__ void __launch_bounds__(256) k_mix(const float* __restrict__ kr,
                                             const float* __restrict__ ki) {
    __shared__ float sKr[64*65];
    __shared__ float sKi[64*65];
    __shared__ float2 sMin[16*64];
    const int kx = blockIdx.x / M2m, ky = blockIdx.x % M2m;
    const int tid = threadIdx.x;
    const size_t kbase = ((size_t)(kx*M2m + ky))*Cc*Cc;
    for (int idx = tid; idx < 64*64; idx += 256) {
        int i = idx >> 6, j = idx & 63;
        sKr[i*65 + j] = kr[kbase + idx];
        sKi[i*65 + j] = ki[kbase + idx];
    }
    for (int idx = tid; idx < 16*64; idx += 256) {
        int bb = idx >> 6, j = idx & 63;
        sMin[idx] = g_M[(((size_t)(bb*M2m + ky))*M1m + kx)*Cc + j];
    }
    __syncthreads();
    const float sc = (ky == 0 ? 1.0f : 2.0f) * (1.0f/65536.0f);
    const int i = tid & 63, bq = tid >> 6;
    float ar[4] = {0,0,0,0}, ai[4] = {0,0,0,0};
    for (int j = 0; j < 64; ++j) {
        float krv = sKr[i*65 + j], kiv = sKi[i*65 + j];
        #pragma unroll
        for (int r = 0; r < 4; ++r) {
            float2 m = sMin[(bq*4 + r)*64 + j];
            ar[r] += krv*m.x - kiv*m.y;
            ai[r] += krv*m.y + kiv*m.x;
        }
    }
    #pragma unroll
    for (int r = 0; r < 4; ++r) {
        int bb = bq*4 + r;
        g_Mo[(((size_t)(bb*M2m + ky))*M1m + kx)*Cc + i] =
            make_float2(ar[r]*sc, ai[r]*sc);
    }
}

// ---------------------------------------------------------------------------
// K4: T[b,h,ky,c] = sum_kx Mo[b,ky,kx,c] * e^{+2*pi*i*(kx-10)*h/H}
// (kept from round 2 — measured 37.8us)
// ---------------------------------------------------------------------------
__global__ void __launch_bounds__(256) k_inv_h() {
    __shared__ float2 sMo[M1m*Cc];
    __shared__ float2 tA[256];   // (cos, sin)
    __shared__ float2 tB[256];   // (-sin, cos)
    const int ky = blockIdx.x, b = blockIdx.y, hc = blockIdx.z;
    const int tid = threadIdx.x;
    {
        float s, c; sincosf((float)tid * TWO_PI_OVER_256, &s, &c);
        tA[tid] = make_float2(c, s);
        tB[tid] = make_float2(-s, c);
    }
    for (int i = tid; i < M1m*Cc; i += 256)
        sMo[i] = g_Mo[((size_t)(b*M2m + ky))*M1m*Cc + i];
    __syncthreads();
    const int cc = tid & 63, hg = tid >> 6;
    double dmr[M1m], dmi[M1m];
    #pragma unroll
    for (int kx = 0; kx < M1m; ++kx) {
        float2 m = sMo[kx*Cc + cc];
        dmr[kx] = dup2(m.x); dmi[kx] = dup2(m.y);
    }
    #pragma unroll 2
    for (int it = 0; it < 16; ++it) {
        int h = hc*64 + hg + 4*it;
        double acc = 0.0;
        int t = (246*h) & 255;
        #pragma unroll
        for (int kx = 0; kx < M1m; ++kx) {
            acc = ffma2(dmr[kx], *(const double*)&tA[t], acc);
            acc = ffma2(dmi[kx], *(const double*)&tB[t], acc);
            t = (t + h) & 255;
        }
        *(double*)&g_T[(((size_t)(b*Hh + h))*M2m + ky)*Cc + cc] = acc;
    }
}

// ---------------------------------------------------------------------------
// K5: unified GEMM.
// out[w,c] = sum_{j<64} P[w,j]*(Wl^T+I)[j,c] + sum_{j<40} CS[w,j]*T'[j,c]
//   CS[w][2k]=cos(k*w*th), CS[w][2k+1]=sin(k*w*th); T'[2k]=Tr[k], T'[2k+1]=-Ti[k]
// block=(h,b); 256 threads; 8w x 4c register tile; 2 passes of 128 w rows
// smem = 80KB -> 2 CTAs/SM
// ---------------------------------------------------------------------------
__global__ void __launch_bounds__(256) k_final(const float* __restrict__ pts,
                                               const float* __restrict__ wl,
                                               float* __restrict__ out) {
    extern __shared__ float sm[];
    float*  sW  = sm;                        // 64x64   (wl^T + I)
    float*  sT  = sW + Cc*Cc;                // 40x64   interleaved Tr / -Ti
    float2* tcs = (float2*)(sT + 2*M2m*Cc);  // 256 (cos,sin)
    float*  sP  = (float*)(tcs + 256);       // 128x64
    float*  sCS = sP + 128*Cc;               // 128x40
    const int h = blockIdx.x, b = blockIdx.y;
    const int tid = threadIdx.x;
    const size_t rowbase = ((size_t)(b*Hh + h))*(Ww*Cc);

    for (int idx = tid; idx < Cc*Cc; idx += 256) {
        int c = idx >> 6, j = idx & 63;
        sW[j*64 + c] = wl[idx] + ((c == j) ? 1.0f : 0.0f);
    }
    {
        const float2* tsrc = g_T + ((size_t)(b*Hh + h))*M2m*Cc;
        for (int i = tid; i < M2m*Cc; i += 256) {
            int k = i >> 6, c = i & 63;
            float2 v = tsrc[i];
            sT[(2*k)*64 + c]   = v.x;
            sT[(2*k+1)*64 + c] = -v.y;
        }
    }
    {
        float s, c; sincosf((float)tid * TWO_PI_OVER_256, &s, &c);
        tcs[tid] = make_float2(c, s);
    }

    const int tc = tid & 15, tw = tid >> 4;
    const int c0 = tc * 4,  w0 = tw * 8;

    for (int pass = 0; pass < 2; ++pass) {
        __syncthreads();   // initial loads done / previous pass consumers done
        // load P rows for this pass
        const float* src = pts + rowbase + (size_t)pass*128*Cc;
        for (int i = tid; i < (128*Cc)/4; i += 256)
            ((float4*)sP)[i] = ((const float4*)src)[i];
        // build CS rows for this pass
        {
            int w = tid & 127, half = tid >> 7;
            int gw = pass*128 + w;
            #pragma unroll
            for (int k = half*10; k < half*10 + 10; ++k) {
                float2 cs = tcs[(k*gw) & 255];
                sCS[w*40 + 2*k]     = cs.x;
                sCS[w*40 + 2*k + 1] = cs.y;
            }
        }
        __syncthreads();

        float acc[8][4];
        #pragma unroll
        for (int w = 0; w < 8; ++w) {
            acc[w][0] = 0.f; acc[w][1] = 0.f; acc[w][2] = 0.f; acc[w][3] = 0.f;
        }

        // linear part: K = 64 over sW
        #pragma unroll 4
        for (int j = 0; j < Cc; j += 4) {
            float4 B0 = *(const float4*)(sW + (j+0)*64 + c0);
            float4 B1 = *(const float4*)(sW + (j+1)*64 + c0);
            float4 B2 = *(const float4*)(sW + (j+2)*64 + c0);
            float4 B3 = *(const float4*)(sW + (j+3)*64 + c0);
            #pragma unroll
            for (int w = 0; w < 8; ++w) {
                float4 p = *(const float4*)(sP + (w0+w)*64 + j);
                acc[w][0] += p.x*B0.x; acc[w][0] += p.y*B1.x;
                acc[w][0] += p.z*B2.x; acc[w][0] += p.w*B3.x;
                acc[w][1] += p.x*B0.y; acc[w][1] += p.y*B1.y;
                acc[w][1] += p.z*B2.y; acc[w][1] += p.w*B3.y;
                acc[w][2] += p.x*B0.z; acc[w][2] += p.y*B1.z;
                acc[w][2] += p.z*B2.z; acc[w][2] += p.w*B3.z;
                acc[w][3] += p.x*B0.w; acc[w][3] += p.y*B1.w;
                acc[w][3] += p.z*B2.w; acc[w][3] += p.w*B3.w;
            }
        }

        // spectral part: K = 40 over sT with CS
        #pragma unroll 2
        for (int j = 0; j < 2*M2m; j += 4) {
            float4 B0 = *(const float4*)(sT + (j+0)*64 + c0);
            float4 B1 = *(const float4*)(sT + (j+1)*64 + c0);
            float4 B2 = *(const float4*)(sT + (j+2)*64 + c0);
            float4 B3 = *(const float4*)(sT + (j+3)*64 + c0);
            #pragma unroll
            for (int w = 0; w < 8; ++w) {
                float4 p = *(const float4*)(sCS + (w0+w)*40 + j);
                acc[w][0] += p.x*B0.x; acc[w][0] += p.y*B1.x;
                acc[w][0] += p.z*B2.x; acc[w][0] += p.w*B3.x;
                acc[w][1] += p.x*B0.y; acc[w][1] += p.y*B1.y;
                acc[w][1] += p.z*B2.y; acc[w][1] += p.w*B3.y;
                acc[w][2] += p.x*B0.z; acc[w][2] += p.y*B1.z;
                acc[w][2] += p.z*B2.z; acc[w][2] += p.w*B3.z;
                acc[w][3] += p.x*B0.w; acc[w][3] += p.y*B1.w;
                acc[w][3] += p.z*B2.w; acc[w][3] += p.w*B3.w;
            }
        }

        // store
        #pragma unroll
        for (int w = 0; w < 8; ++w) {
            float* op = out + rowbase + (size_t)(pass*128 + w0 + w)*Cc + c0;
            *(float4*)op = make_float4(acc[w][0], acc[w][1], acc[w][2], acc[w][3]);
        }
    }
}

// ---------------------------------------------------------------------------
extern "C" void kernel_launch(void* const* d_in, const int* in_sizes, int n_in,
                              void* d_out, int out_size) {
    (void)in_sizes; (void)n_in; (void)out_size;
    const float* pts = (const float*)d_in[0];
    const float* kr  = (const float*)d_in[1];
    const float* ki  = (const float*)d_in[2];
    const float* wl  = (const float*)d_in[3];
    float* out = (float*)d_out;

    const int sm1 = Ww*Cc*(int)sizeof(float) + 256*(int)sizeof(float2);   // ~66 KB
    const int sm5 = (Cc*Cc + 2*M2m*Cc + 128*Cc + 128*2*M2m)*(int)sizeof(float)
                  + 256*(int)sizeof(float2);                              // 80 KB
    cudaFuncSetAttribute(k_fwd_w, cudaFuncAttributeMaxDynamicSharedMemorySize, sm1);
    cudaFuncSetAttribute(k_final, cudaFuncAttributeMaxDynamicSharedMemorySize, sm5);

    k_fwd_w<<<dim3(Hh, Bb), 160, sm1>>>(pts);
    k_fwd_h<<<dim3(M2m, Bb), 128>>>();
    k_mix  <<<M1m*M2m, 256>>>(kr, ki);
    k_inv_h<<<dim3(M2m, Bb, 4), 256>>>();
    k_final<<<dim3(Hh, Bb), 256, sm5>>>(pts, wl, out);
}

// round 4
// speedup vs baseline: 1.5971x; 1.5306x over previous
#include <cuda_runtime.h>

#define Bb 16
#define Hh 256
#define Ww 256
#define Cc 64
#define M1m 20
#define M2m 20

// Scratch (device globals; no allocation allowed)
__device__ float2 g_A [Bb*Hh*M2m*Cc];   // forward w-transform   [b][h][ky][c]
__device__ float2 g_M [Bb*M2m*M1m*Cc];  // forward modes         [b][ky][kx][c]
__device__ float2 g_Mo[Bb*M2m*M1m*Cc];  // mixed modes (scaled)  [b][ky][kx][c]
__device__ float2 g_T [Bb*Hh*M2m*Cc];   // inverse h-expand      [b][h][ky][c]

#define TWO_PI_OVER_256 0.0245436926061702596f

// ---- f32x2 helpers (K2/K4 only) --------------------------------------------
__device__ __forceinline__ double ffma2(double a, double b, double c) {
    double d;
    asm("fma.rn.f32x2 %0, %1, %2, %3;" : "=d"(d) : "d"(a), "d"(b), "d"(c));
    return d;
}
__device__ __forceinline__ double dup2(float x) {
    double d; asm("mov.b64 %0, {%1, %1};" : "=d"(d) : "f"(x)); return d;
}
__device__ __forceinline__ float2 up2(double d) {
    float2 f; asm("mov.b64 {%0, %1}, %2;" : "=f"(f.x), "=f"(f.y) : "d"(d));
    return f;
}

// ---------------------------------------------------------------------------
// K1: A[b,h,ky,c] = sum_w P*e^{-i ky w th}
// mod-2 fold over w: A[ky] = sum_{w'<128} (P[w'] +- P[w'+128]) e^{-i ky w' th}
// block=(h,b); 320 threads = 20 ky * 8 cgroups(8c) * 2 wsplit
// ---------------------------------------------------------------------------
__global__ void __launch_bounds__(320) k_fwd_w(const float* __restrict__ pts) {
    extern __shared__ float sm[];
    float*  sPp = sm;                       // [128][64]  P[w']+P[w'+128]
    float*  sPm = sm + 8192;                // [128][64]  P[w']-P[w'+128]
    float2* tcs = (float2*)(sm + 16384);    // 256 x (cos, -sin)
    const int h = blockIdx.x, b = blockIdx.y;
    const int tid = threadIdx.x;
    const float4* prow = (const float4*)(pts + ((size_t)(b*Hh + h))*(Ww*Cc));
    for (int i = tid; i < 2048; i += 320) {
        float4 a = prow[i], c = prow[i + 2048];
        ((float4*)sPp)[i] = make_float4(a.x+c.x, a.y+c.y, a.z+c.z, a.w+c.w);
        ((float4*)sPm)[i] = make_float4(a.x-c.x, a.y-c.y, a.z-c.z, a.w-c.w);
    }
    if (tid < 256) {
        float s, c; sincosf((float)tid * TWO_PI_OVER_256, &s, &c);
        tcs[tid] = make_float2(c, -s);
    }
    __syncthreads();

    const int ws = tid & 1;
    const int cg = (tid >> 1) & 7;
    const int ky = tid >> 4;              // 0..19
    const int c0 = cg * 8;
    const float* plane = (ky & 1) ? sPm : sPp;

    float r[8], q[8];
    #pragma unroll
    for (int k = 0; k < 8; ++k) { r[k] = 0.f; q[k] = 0.f; }

    const int wbeg = ws * 64;
    int t = (ky * wbeg) & 255;
    #pragma unroll 4
    for (int w = wbeg; w < wbeg + 64; ++w) {
        const float* pr = plane + w*64 + c0;
        float4 pA = *(const float4*)(pr);
        float4 pB = *(const float4*)(pr + 4);
        float2 cs = tcs[t];
        float cv = cs.x, ns = cs.y;
        r[0] += pA.x*cv; q[0] += pA.x*ns;
        r[1] += pA.y*cv; q[1] += pA.y*ns;
        r[2] += pA.z*cv; q[2] += pA.z*ns;
        r[3] += pA.w*cv; q[3] += pA.w*ns;
        r[4] += pB.x*cv; q[4] += pB.x*ns;
        r[5] += pB.y*cv; q[5] += pB.y*ns;
        r[6] += pB.z*cv; q[6] += pB.z*ns;
        r[7] += pB.w*cv; q[7] += pB.w*ns;
        t = (t + ky) & 255;
    }

    __syncthreads();
    if (ws == 1) {
        float* buf = sPp + (ky*8 + cg)*16;
        #pragma unroll
        for (int k = 0; k < 8; ++k) { buf[k] = r[k]; buf[8+k] = q[k]; }
    }
    __syncthreads();
    if (ws == 0) {
        const float* buf = sPp + (ky*8 + cg)*16;
        #pragma unroll
        for (int k = 0; k < 8; ++k) { r[k] += buf[k]; q[k] += buf[8+k]; }
        float2* dst = g_A + (((size_t)(b*Hh + h))*M2m + ky)*Cc + c0;
        #pragma unroll
        for (int k = 0; k < 4; ++k)
            *(float4*)(dst + 2*k) = make_float4(r[2*k], q[2*k], r[2*k+1], q[2*k+1]);
    }
}

// ---------------------------------------------------------------------------
// K2: M[b,ky,kx,c] = sum_h A*e^{-i(kx-10)h th}
// mod-2 fold over h: even kx use A[h']+A[h'+128], odd use A[h']-A[h'+128]
// 128 threads = 2 parity-groups(10 kx as 5 f32x2 pairs) * 64 c
// ---------------------------------------------------------------------------
#define HT2 32
__global__ void __launch_bounds__(128) k_fwd_h() {
    __shared__ float2 sAp[HT2*Cc];          // A[h']+A[h'+128]
    __shared__ float2 sAm[HT2*Cc];          // A[h']-A[h'+128]
    __shared__ float sCv[HT2*M1m];          // cos per (hh, j)  j->kx=2j+kg
    __shared__ float sSv[HT2*M1m];
    __shared__ float2 tbl[256];
    const int ky = blockIdx.x, b = blockIdx.y;
    const int tid = threadIdx.x;
    for (int i = tid; i < 256; i += 128) {
        float s, c; sincosf((float)i * TWO_PI_OVER_256, &s, &c);
        tbl[i] = make_float2(c, s);
    }
    const int cc = tid & 63, kg = tid >> 6;   // kg = kx parity
    double aar[5] = {0,0,0,0,0}, aai[5] = {0,0,0,0,0};
    __syncthreads();

    for (int h0 = 0; h0 < 128; h0 += HT2) {
        __syncthreads();
        for (int i = tid; i < HT2*Cc; i += 128) {
            int hh = i >> 6, c = i & 63;
            float2 a0 = g_A[(((size_t)(b*Hh + h0 + hh))*M2m + ky)*Cc + c];
            float2 a1 = g_A[(((size_t)(b*Hh + h0 + hh + 128))*M2m + ky)*Cc + c];
            sAp[i] = make_float2(a0.x + a1.x, a0.y + a1.y);
            sAm[i] = make_float2(a0.x - a1.x, a0.y - a1.y);
        }
        for (int i = tid; i < HT2*M1m; i += 128) {
            int hh = i / M1m, jj = i - hh*M1m;
            int kgg = jj / 10, j = jj - kgg*10;
            int kx = 2*j + kgg;
            float2 cs = tbl[((kx + 246) * (h0 + hh)) & 255];
            sCv[i] = cs.x; sSv[i] = cs.y;
        }
        __syncthreads();
        const float2* plane = kg ? sAm : sAp;
        #pragma unroll 2
        for (int hh = 0; hh < HT2; ++hh) {
            float2 a = plane[hh*Cc + cc];
            double dax = dup2(a.x), day = dup2(a.y), dnx = dup2(-a.x);
            const float* cvp = sCv + hh*M1m + kg*10;
            const float* svp = sSv + hh*M1m + kg*10;
            #pragma unroll
            for (int p = 0; p < 5; ++p) {
                double cp = *(const double*)(cvp + 2*p);
                double sp = *(const double*)(svp + 2*p);
                aar[p] = ffma2(dax, cp, aar[p]);
                aar[p] = ffma2(day, sp, aar[p]);
                aai[p] = ffma2(day, cp, aai[p]);
                aai[p] = ffma2(dnx, sp, aai[p]);
            }
        }
    }
    #pragma unroll
    for (int p = 0; p < 5; ++p) {
        // f32x2 lanes = j=2p (kx=4p+kg) and j=2p+1 (kx=4p+2+kg)
        float2 r = up2(aar[p]), im = up2(aai[p]);
        int kx0 = 4*p + kg;
        size_t base = (((size_t)(b*M2m + ky))*M1m)*Cc + cc;
        g_M[base + (size_t)kx0*Cc]       = make_float2(r.x, im.x);
        g_M[base + (size_t)(kx0+2)*Cc]   = make_float2(r.y, im.y);
    }
}

// ---------------------------------------------------------------------------
// K3: channel mix (complex 64x64 per mode) + fold alpha_ky/(H*W)
// ---------------------------------------------------------------------------
__global__ void __launch_bounds__(256) k_mix(const float* __restrict__ kr,
                                             const float* __restrict__ ki) {
    __shared__ float sKr[64*65];
    __shared__ float sKi[64*65];
    __shared__ float2 sMin[16*64];
    const int kx = blockIdx.x / M2m, ky = blockIdx.x % M2m;
    const int tid = threadIdx.x;
    const size_t kbase = ((size_t)(kx*M2m + ky))*Cc*Cc;
    for (int idx = tid; idx < 64*64; idx += 256) {
        int i = idx >> 6, j = idx & 63;
        sKr[i*65 + j] = kr[kbase + idx];
        sKi[i*65 + j] = ki[kbase + idx];
    }
    for (int idx = tid; idx < 16*64; idx += 256) {
        int bb = idx >> 6, j = idx & 63;
        sMin[idx] = g_M[(((size_t)(bb*M2m + ky))*M1m + kx)*Cc + j];
    }
    __syncthreads();
    const float sc = (ky == 0 ? 1.0f : 2.0f) * (1.0f/65536.0f);
    const int i = tid & 63, bq = tid >> 6;
    float ar[4] = {0,0,0,0}, ai[4] = {0,0,0,0};
    for (int j = 0; j < 64; ++j) {
        float krv = sKr[i*65 + j], kiv = sKi[i*65 + j];
        #pragma unroll
        for (int r = 0; r < 4; ++r) {
            float2 m = sMin[(bq*4 + r)*64 + j];
            ar[r] += krv*m.x - kiv*m.y;
            ai[r] += krv*m.y + kiv*m.x;
        }
    }
    #pragma unroll
    for (int r = 0; r < 4; ++r) {
        int bb = bq*4 + r;
        g_Mo[(((size_t)(bb*M2m + ky))*M1m + kx)*Cc + i] =
            make_float2(ar[r]*sc, ai[r]*sc);
    }
}

// ---------------------------------------------------------------------------
// K4: T[b,h,ky,c] = sum_kx Mo*e^{+i(kx-10)h th}
// mod-2 fold over h: Se/So by kx parity; T[h]=Se+So, T[h+128]=Se-So
// block=(ky,b,hc of 2); 256 threads = 4 hgroups * 64 c
// ---------------------------------------------------------------------------
__global__ void __launch_bounds__(256) k_inv_h() {
    __shared__ float2 sMo[M1m*Cc];
    __shared__ float2 tA[256];   // (cos, sin)
    __shared__ float2 tB[256];   // (-sin, cos)
    const int ky = blockIdx.x, b = blockIdx.y, hc = blockIdx.z;
    const int tid = threadIdx.x;
    {
        float s, c; sincosf((float)tid * TWO_PI_OVER_256, &s, &c);
        tA[tid] = make_float2(c, s);
        tB[tid] = make_float2(-s, c);
    }
    for (int i = tid; i < M1m*Cc; i += 256)
        sMo[i] = g_Mo[((size_t)(b*M2m + ky))*M1m*Cc + i];
    __syncthreads();
    const int cc = tid & 63, hg = tid >> 6;
    double dmr[M1m], dmi[M1m];
    #pragma unroll
    for (int kx = 0; kx < M1m; ++kx) {
        float2 m = sMo[kx*Cc + cc];
        dmr[kx] = dup2(m.x); dmi[kx] = dup2(m.y);
    }
    #pragma unroll 2
    for (int it = 0; it < 16; ++it) {
        int h = hc*64 + hg + 4*it;            // h in [0,128)
        double ae = 0.0, ao = 0.0;
        int t = (246*h) & 255;
        #pragma unroll
        for (int kx = 0; kx < M1m; ++kx) {
            double ta = *(const double*)&tA[t];
            double tb = *(const double*)&tB[t];
            if (kx & 1) {
                ao = ffma2(dmr[kx], ta, ao);
                ao = ffma2(dmi[kx], tb, ao);
            } else {
                ae = ffma2(dmr[kx], ta, ae);
                ae = ffma2(dmi[kx], tb, ae);
            }
            t = (t + h) & 255;
        }
        float2 fe = up2(ae), fo = up2(ao);
        size_t base = (((size_t)(b*Hh + h))*M2m + ky)*Cc + cc;
        g_T[base]                       = make_float2(fe.x + fo.x, fe.y + fo.y);
        g_T[base + (size_t)128*M2m*Cc]  = make_float2(fe.x - fo.x, fe.y - fo.y);
    }
}

// ---------------------------------------------------------------------------
// K5: out[w,c] = spectral + P @ (Wl^T + I)
// spectral mod-2 over w: R0 (even ky) + R1 (odd ky), out[w]=R0+R1,
// out[w+128]=R0-R1; R real sums only (21 FMA/out vs 40).
// block=(h,b); 256 threads = 32 wgroups * 8 cgroups; thread tile 8rows x 8c
// ---------------------------------------------------------------------------
__global__ void __launch_bounds__(256, 2) k_final(const float* __restrict__ pts,
                                                  const float* __restrict__ wl,
                                                  float* __restrict__ out) {
    extern __shared__ float sm[];
    float*  sW  = sm;                        // [j][c] 64x64 (wl^T + I)
    float*  sTe = sm + 4096;                 // 10 x {Tr row, -Ti row} even ky
    float*  sTo = sTe + 1280;                // 10 x {Tr row, -Ti row} odd ky
    float2* tcs = (float2*)(sTo + 1280);     // 256 (cos, sin)
    float*  sP  = (float*)(tcs + 256);       // [256][64]
    const int h = blockIdx.x, b = blockIdx.y;
    const int tid = threadIdx.x;
    const size_t rowbase = ((size_t)(b*Hh + h))*(Ww*Cc);

    for (int idx = tid; idx < Cc*Cc; idx += 256) {
        int c = idx >> 6, j = idx & 63;
        sW[j*64 + c] = wl[idx] + ((c == j) ? 1.0f : 0.0f);
    }
    {
        const float2* tsrc = g_T + ((size_t)(b*Hh + h))*M2m*Cc;
        for (int i = tid; i < M2m*Cc; i += 256) {
            int ky = i >> 6, c = i & 63;
            float2 v = tsrc[i];
            float* basep = (ky & 1) ? sTo : sTe;
            int e = ky >> 1;
            basep[e*128 + c]      = v.x;
            basep[e*128 + 64 + c] = -v.y;
        }
    }
    {
        float s, c; sincosf((float)tid * TWO_PI_OVER_256, &s, &c);
        tcs[tid] = make_float2(c, s);
    }
    for (int i = tid; i < (Ww*Cc)/4; i += 256)
        ((float4*)sP)[i] = ((const float4*)(pts + rowbase))[i];
    __syncthreads();

    const int cg = tid & 7, wpg = tid >> 3;   // wpg 0..31
    const int c0 = cg * 8;
    const int wbase = wpg * 4;                // 4 wb rows + their +128 images

    float acc[8][8];                          // [k<4: wb rows][4+k: wb+128 rows]
    #pragma unroll
    for (int i = 0; i < 8; ++i)
        #pragma unroll
        for (int k = 0; k < 8; ++k) acc[i][k] = 0.f;

    // ---- spectral (two passes of 2 wb rows to bound registers) ----
    #pragma unroll
    for (int pass = 0; pass < 2; ++pass) {
        const int wb0 = wbase + pass*2;
        float Re[2][8], Ro[2][8];
        #pragma unroll
        for (int pp = 0; pp < 2; ++pp)
            #pragma unroll
            for (int k = 0; k < 8; ++k) { Re[pp][k] = 0.f; Ro[pp][k] = 0.f; }

        #pragma unroll
        for (int e = 0; e < 10; ++e) {          // even ky = 2e
            const float* row = sTe + e*128;
            float4 t0 = *(const float4*)(row + c0);
            float4 t1 = *(const float4*)(row + c0 + 4);
            float4 n0 = *(const float4*)(row + 64 + c0);
            float4 n1 = *(const float4*)(row + 64 + c0 + 4);
            #pragma unroll
            for (int pp = 0; pp < 2; ++pp) {
                float2 cs = tcs[(2*e*(wb0+pp)) & 255];
                float cv = cs.x, sv = cs.y;
                Re[pp][0] += t0.x*cv; Re[pp][0] += n0.x*sv;
                Re[pp][1] += t0.y*cv; Re[pp][1] += n0.y*sv;
                Re[pp][2] += t0.z*cv; Re[pp][2] += n0.z*sv;
                Re[pp][3] += t0.w*cv; Re[pp][3] += n0.w*sv;
                Re[pp][4] += t1.x*cv; Re[pp][4] += n1.x*sv;
                Re[pp][5] += t1.y*cv; Re[pp][5] += n1.y*sv;
                Re[pp][6] += t1.z*cv; Re[pp][6] += n1.z*sv;
                Re[pp][7] += t1.w*cv; Re[pp][7] += n1.w*sv;
            }
        }
        #pragma unroll
        for (int e = 0; e < 10; ++e) {          // odd ky = 2e+1
            const float* row = sTo + e*128;
            float4 t0 = *(const float4*)(row + c0);
            float4 t1 = *(const float4*)(row + c0 + 4);
            float4 n0 = *(const float4*)(row + 64 + c0);
            float4 n1 = *(const float4*)(row + 64 + c0 + 4);
            #pragma unroll
            for (int pp = 0; pp < 2; ++pp) {
                float2 cs = tcs[((2*e+1)*(wb0+pp)) & 255];
                float cv = cs.x, sv = cs.y;
                Ro[pp][0] += t0.x*cv; Ro[pp][0] += n0.x*sv;
                Ro[pp][1] += t0.y*cv; Ro[pp][1] += n0.y*sv;
                Ro[pp][2] += t0.z*cv; Ro[pp][2] += n0.z*sv;
                Ro[pp][3] += t0.w*cv; Ro[pp][3] += n0.w*sv;
                Ro[pp][4] += t1.x*cv; Ro[pp][4] += n1.x*sv;
                Ro[pp][5] += t1.y*cv; Ro[pp][5] += n1.y*sv;
                Ro[pp][6] += t1.z*cv; Ro[pp][6] += n1.z*sv;
                Ro[pp][7] += t1.w*cv; Ro[pp][7] += n1.w*sv;
            }
        }
        #pragma unroll
        for (int pp = 0; pp < 2; ++pp) {
            int k = pass*2 + pp;
            #pragma unroll
            for (int c = 0; c < 8; ++c) {
                acc[k][c]     += Re[pp][c] + Ro[pp][c];
                acc[4 + k][c] += Re[pp][c] - Ro[pp][c];
            }
        }
    }

    // ---- linear GEMM: 8 rows (wbase+k, wbase+k+128) x 8c, K=64 ----
    #pragma unroll 2
    for (int j = 0; j < Cc; j += 4) {
        float4 B0a = *(const float4*)(sW + (j+0)*64 + c0);
        float4 B0b = *(const float4*)(sW + (j+0)*64 + c0 + 4);
        float4 B1a = *(const float4*)(sW + (j+1)*64 + c0);
        float4 B1b = *(const float4*)(sW + (j+1)*64 + c0 + 4);
        float4 B2a = *(const float4*)(sW + (j+2)*64 + c0);
        float4 B2b = *(const float4*)(sW + (j+2)*64 + c0 + 4);
        float4 B3a = *(const float4*)(sW + (j+3)*64 + c0);
        float4 B3b = *(const float4*)(sW + (j+3)*64 + c0 + 4);
        #pragma unroll
        for (int k = 0; k < 8; ++k) {
            int row = (k < 4) ? (wbase + k) : (wbase + k - 4 + 128);
            float4 p = *(const float4*)(sP + row*64 + j);
            acc[k][0] += p.x*B0a.x; acc[k][0] += p.y*B1a.x;
            acc[k][0] += p.z*B2a.x; acc[k][0] += p.w*B3a.x;
            acc[k][1] += p.x*B0a.y; acc[k][1] += p.y*B1a.y;
            acc[k][1] += p.z*B2a.y; acc[k][1] += p.w*B3a.y;
            acc[k][2] += p.x*B0a.z; acc[k][2] += p.y*B1a.z;
            acc[k][2] += p.z*B2a.z; acc[k][2] += p.w*B3a.z;
            acc[k][3] += p.x*B0a.w; acc[k][3] += p.y*B1a.w;
            acc[k][3] += p.z*B2a.w; acc[k][3] += p.w*B3a.w;
            acc[k][4] += p.x*B0b.x; acc[k][4] += p.y*B1b.x;
            acc[k][4] += p.z*B2b.x; acc[k][4] += p.w*B3b.x;
            acc[k][5] += p.x*B0b.y; acc[k][5] += p.y*B1b.y;
            acc[k][5] += p.z*B2b.y; acc[k][5] += p.w*B3b.y;
            acc[k][6] += p.x*B0b.z; acc[k][6] += p.y*B1b.z;
            acc[k][6] += p.z*B2b.z; acc[k][6] += p.w*B3b.z;
            acc[k][7] += p.x*B0b.w; acc[k][7] += p.y*B1b.w;
            acc[k][7] += p.z*B2b.w; acc[k][7] += p.w*B3b.w;
        }
    }

    // ---- store ----
    #pragma unroll
    for (int k = 0; k < 8; ++k) {
        int row = (k < 4) ? (wbase + k) : (wbase + k - 4 + 128);
        float* op = out + rowbase + (size_t)row*Cc + c0;
        *(float4*)(op)     = make_float4(acc[k][0], acc[k][1], acc[k][2], acc[k][3]);
        *(float4*)(op + 4) = make_float4(acc[k][4], acc[k][5], acc[k][6], acc[k][7]);
    }
}

// ---------------------------------------------------------------------------
extern "C" void kernel_launch(void* const* d_in, const int* in_sizes, int n_in,
                              void* d_out, int out_size) {
    (void)in_sizes; (void)n_in; (void)out_size;
    const float* pts = (const float*)d_in[0];
    const float* kr  = (const float*)d_in[1];
    const float* ki  = (const float*)d_in[2];
    const float* wl  = (const float*)d_in[3];
    float* out = (float*)d_out;

    const int sm1 = (16384 + 512) * (int)sizeof(float);                 // 66 KB
    const int sm5 = (4096 + 1280 + 1280 + 512 + 16384)*(int)sizeof(float); // 92 KB
    cudaFuncSetAttribute(k_fwd_w, cudaFuncAttributeMaxDynamicSharedMemorySize, sm1);
    cudaFuncSetAttribute(k_final, cudaFuncAttributeMaxDynamicSharedMemorySize, sm5);

    k_fwd_w<<<dim3(Hh, Bb), 320, sm1>>>(pts);
    k_fwd_h<<<dim3(M2m, Bb), 128>>>();
    k_mix  <<<M1m*M2m, 256>>>(kr, ki);
    k_inv_h<<<dim3(M2m, Bb, 2), 256>>>();
    k_final<<<dim3(Hh, Bb), 256, sm5>>>(pts, wl, out);
}